// round 4
// baseline (speedup 1.0000x reference)
#include <cuda_runtime.h>
#include <stdint.h>

#define BB 16
#define PP 131072
#define NC 21
#define CM1 20
#define TOPK 400
#define KEEPK 200
#define GCAP 4608
#define NEGV (-1000000000.0f)
#define SAMP 4096
#define KSEL 64
#define NPAIR (BB * CM1) /* 320 */
#define TILE_P 4096
#define SCAP 192
#define SUPW 13 /* ceil(400/32) */

// ---------------- device scratch ----------------
__device__ float g_tlo[BB][NC];
__device__ int g_cnt[NPAIR];
__device__ unsigned long long g_cand[NPAIR][GCAP];
__device__ int g_kc[NPAIR];
__device__ unsigned long long g_ck[NPAIR * KEEPK];
__device__ float4 g_fb[BB * CM1 * TOPK];

// ---- warp-parallel bucket selection over 64-bucket histogram --------------
// Picks max bucket b with suffix-sum S[b] >= k (reference semantics), writes
// {bsel, k - cum_above, hist[bsel]} to shared. Call with threads 0..31.
__device__ __forceinline__ void warp_bucket_sel(const int* hist, int k,
                                                int* sh_b, int* sh_k, int* sh_c) {
    int lane = threadIdx.x & 31;
    int h0 = hist[2 * lane], h1 = hist[2 * lane + 1];
    int s = h0 + h1;
#pragma unroll
    for (int off = 1; off < 32; off <<= 1) {
        int v = __shfl_down_sync(0xFFFFFFFFu, s, off);
        if (lane + off < 32) s += v;
    }
    int S0 = s, S1 = s - h0;           // suffix sums at buckets 2l, 2l+1
    int cand = -1, Sc = 0;
    if (S1 >= k)      { cand = 2 * lane + 1; Sc = S1; }
    else if (S0 >= k) { cand = 2 * lane;     Sc = S0; }
    unsigned bal = __ballot_sync(0xFFFFFFFFu, cand >= 0);
    int bsel, cum;
    if (bal) {
        int src = 31 - __clz(bal);
        bsel = __shfl_sync(0xFFFFFFFFu, cand, src);
        int Sb = __shfl_sync(0xFFFFFFFFu, Sc, src);
        cum = Sb - hist[bsel];
    } else {
        int tot = __shfl_sync(0xFFFFFFFFu, S0, 0);
        bsel = 0;
        cum = tot - hist[0];
    }
    if (lane == 0) { *sh_b = bsel; *sh_k = k - cum; *sh_c = hist[bsel]; }
}

// ---- exact k-th largest among n distinct u64 keys (shared-mem array) ------
__device__ unsigned long long radix_select_k(const unsigned long long* arr, int n, int k,
                                             int* hist, unsigned long long* sh_pref,
                                             int* sh_b, int* sh_k, int* sh_c) {
    int tid = threadIdx.x, bd = blockDim.x;
    unsigned long long prefix = 0, pmask = 0;
    for (int r = 0; r < 11; r++) {
        int shift = 60 - 6 * r;
        if (tid < 64) hist[tid] = 0;
        __syncthreads();
        for (int i = tid; i < n; i += bd) {
            unsigned long long u = arr[i];
            if ((u & pmask) == prefix) atomicAdd(&hist[(int)((u >> shift) & 63)], 1);
        }
        __syncthreads();
        if (tid < 32) warp_bucket_sel(hist, k, sh_b, sh_k, sh_c);
        __syncthreads();
        prefix |= ((unsigned long long)(*sh_b)) << shift;
        k = *sh_k;
        int cnt = *sh_c;
        pmask |= (63ULL << shift);
        if (cnt == 1) {   // unique survivor: find it and finish (uniform branch)
            __syncthreads();
            for (int i = tid; i < n; i += bd) {
                unsigned long long u = arr[i];
                if ((u & pmask) == prefix) *sh_pref = u;
            }
            __syncthreads();
            return *sh_pref;
        }
    }
    return prefix;
}

// ---------------- K1: per-(b,c) adaptive threshold -------------------------
__global__ void k_thresh(const float* __restrict__ conf) {
    int bc = blockIdx.x;
    int b = bc / CM1, c = bc % CM1 + 1;
    __shared__ unsigned sm[SAMP];
    __shared__ int hist[64];
    __shared__ int sh_b, sh_k, sh_c;
    int tid = threadIdx.x;
    if (tid == 0) g_cnt[bc] = 0;

    const size_t base = (size_t)b * PP * NC + (size_t)c;
    for (int i = tid; i < SAMP; i += blockDim.x) {
        float s = conf[base + (size_t)(i * (PP / SAMP)) * NC];
        sm[i] = __float_as_uint(fmaxf(s, 0.0f));
    }

    unsigned prefix = 0, pmask = 0;
    int k = KSEL;
    for (int r = 0; r < 5; r++) {
        int shift = 26 - 6 * r;
        if (tid < 64) hist[tid] = 0;
        __syncthreads();
        for (int i = tid; i < SAMP; i += blockDim.x) {
            unsigned u = sm[i];
            if ((u & pmask) == prefix) atomicAdd(&hist[(u >> shift) & 63], 1);
        }
        __syncthreads();
        if (tid < 32) warp_bucket_sel(hist, k, &sh_b, &sh_k, &sh_c);
        __syncthreads();
        prefix |= (unsigned)sh_b << shift;
        k = sh_k;
        pmask |= (63u << shift);
    }
    if (tid == 0) g_tlo[b][c] = __uint_as_float(prefix);
}

// ---------------- K2: single coalesced pass over conf ----------------------
__device__ __forceinline__ void k2_push(float s, int e, int pbase,
                                        const float* th, int* scnt,
                                        unsigned long long (*sc)[SCAP], int bbc) {
    if (s > 0.01f) {
        int pl = e / NC;
        int c = e - pl * NC;
        if (s >= th[c]) {
            int cc = c - 1;
            unsigned long long ent =
                ((unsigned long long)__float_as_uint(s) << 32) |
                (unsigned)(0xFFFFFFFFu - (unsigned)(pbase + pl));
            int pos = atomicAdd(&scnt[cc], 1);
            if (pos < SCAP) {
                sc[cc][pos] = ent;
            } else {
                int gp = atomicAdd(&g_cnt[bbc + cc], 1);
                if (gp < GCAP) g_cand[bbc + cc][gp] = ent;
            }
        }
    }
}

__global__ void __launch_bounds__(1024) k_collect(const float* __restrict__ conf) {
    int b = blockIdx.x >> 5;
    int tile = blockIdx.x & 31;
    __shared__ float th[NC];
    __shared__ int scnt[CM1];
    __shared__ unsigned long long sc[CM1][SCAP];
    int tid = threadIdx.x;
    if (tid < NC) th[tid] = (tid == 0) ? 3.0e38f : g_tlo[b][tid];
    if (tid < CM1) scnt[tid] = 0;
    __syncthreads();

    const size_t base = (size_t)b * PP * NC + (size_t)tile * TILE_P * NC;
    const int pbase = tile * TILE_P;
    const int bbc = b * CM1;
    const float4* cp = (const float4*)(conf + base);
    const int NV = TILE_P * NC / 4;
    for (int t = tid; t < NV; t += 1024) {
        float4 v = cp[t];
        int e = 4 * t;
        k2_push(v.x, e, pbase, th, scnt, sc, bbc);
        k2_push(v.y, e + 1, pbase, th, scnt, sc, bbc);
        k2_push(v.z, e + 2, pbase, th, scnt, sc, bbc);
        k2_push(v.w, e + 3, pbase, th, scnt, sc, bbc);
    }
    __syncthreads();
    int w = tid >> 5, lane = tid & 31;
    if (w < CM1) {
        int n = min(scnt[w], SCAP);
        int gb = 0;
        if (lane == 0) gb = atomicAdd(&g_cnt[bbc + w], n);
        gb = __shfl_sync(0xFFFFFFFFu, gb, 0);
        for (int j = lane; j < n; j += 32) {
            int gp = gb + j;
            if (gp < GCAP) g_cand[bbc + w][gp] = sc[w][j];
        }
    }
}

// ---------------- K3: per-(b,c) top-400 select + decode + NMS --------------
// dyn smem: arr[GCAP] u64 (reused as s_srt) | arr2[512] u64 | s_sc[400] |
//           s_bx[400] f4 | s_ar[400] | s_sup[400*13] u32
#define OFF_ARR2  (GCAP * 8)                 /* 36864 */
#define OFF_SSC   (OFF_ARR2 + 512 * 8)       /* 40960 */
#define OFF_SBX   (OFF_SSC + TOPK * 4)       /* 42560 */
#define OFF_SAR   (OFF_SBX + TOPK * 16)      /* 48960 */
#define OFF_SUP   (OFF_SAR + TOPK * 4)       /* 50560 */
#define K3_SMEM   (OFF_SUP + TOPK * SUPW * 4)
__global__ void __launch_bounds__(1024) k_select(const float* __restrict__ loc,
                                                 const float* __restrict__ prior) {
    extern __shared__ unsigned char smraw[];
    unsigned long long* arr = (unsigned long long*)smraw;
    unsigned long long* s_srt = (unsigned long long*)smraw;   // alias, used after arr dead
    unsigned long long* arr2 = (unsigned long long*)(smraw + OFF_ARR2);
    float* s_sc = (float*)(smraw + OFF_SSC);
    float4* s_bx = (float4*)(smraw + OFF_SBX);
    float* s_ar = (float*)(smraw + OFF_SAR);
    unsigned* s_sup = (unsigned*)(smraw + OFF_SUP);
    __shared__ int hist[64];
    __shared__ unsigned long long sh_pref;
    __shared__ int sh_b, sh_k, sh_c, sh_cpos;
    __shared__ unsigned keepw[SUPW];
    __shared__ int pref_keep[SUPW];
    int bc = blockIdx.x;
    int b = bc / CM1, cc = bc % CM1;
    int tid = threadIdx.x;

    int n = min(g_cnt[bc], GCAP);
    for (int t = tid; t < n; t += blockDim.x) arr[t] = g_cand[bc][t];
    if (tid == 0) sh_cpos = 0;
    __syncthreads();

    int K = min(n, TOPK);
    unsigned long long kth = 0;
    if (n > TOPK) kth = radix_select_k(arr, n, K, hist, &sh_pref, &sh_b, &sh_k, &sh_c);

    // compact exactly K survivors (keys distinct)
    for (int i = tid; i < n; i += blockDim.x) {
        unsigned long long u = arr[i];
        if (u >= kth && u != 0ULL) {
            int pos = atomicAdd(&sh_cpos, 1);
            if (pos < 512) arr2[pos] = u;
        }
    }
    __syncthreads();

    // rank-sort: rank = #greater keys (distinct keys -> permutation)
    for (int t = tid; t < K; t += blockDim.x) {
        unsigned long long my = arr2[t];
        int rk = 0;
        for (int j = 0; j < K; j++) rk += (arr2[j] > my);
        s_srt[rk] = my;
    }
    __syncthreads();

    int M = K;
    const float4* loc4 = (const float4*)loc + (size_t)b * PP;
    const float4* pri4 = (const float4*)prior;
    for (int t = tid; t < TOPK; t += blockDim.x) {
        if (t < M) {
            unsigned long long e = s_srt[t];
            unsigned idx = 0xFFFFFFFFu - (unsigned)(e & 0xFFFFFFFFu);
            float4 l = loc4[idx];
            float4 pb = pri4[idx];
            float cx = __fmul_rn(__fadd_rn(pb.x, pb.z), 0.5f);
            float cy = __fmul_rn(__fadd_rn(pb.y, pb.w), 0.5f);
            float swd = __fsub_rn(pb.z, pb.x);
            float shg = __fsub_rn(pb.w, pb.y);
            float x = __fadd_rn(cx, __fmul_rn(__fmul_rn(l.x, 0.1f), swd));
            float y = __fadd_rn(cy, __fmul_rn(__fmul_rn(l.y, 0.1f), shg));
            float w = __fmul_rn(swd, expf(__fmul_rn(l.z, 0.2f)));
            float h = __fmul_rn(shg, expf(__fmul_rn(l.w, 0.2f)));
            float x1 = __fsub_rn(x, __fmul_rn(w, 0.5f));
            float y1 = __fsub_rn(y, __fmul_rn(h, 0.5f));
            float x2 = __fadd_rn(x1, w);
            float y2 = __fadd_rn(y1, h);
            s_sc[t] = __uint_as_float((unsigned)(e >> 32));
            s_bx[t] = make_float4(x1, y1, x2, y2);
            s_ar[t] = __fmul_rn(__fsub_rn(x2, x1), __fsub_rn(y2, y1));
        } else {
            s_sc[t] = NEGV;
            s_bx[t] = make_float4(0.f, 0.f, 0.f, 0.f);
            s_ar[t] = 0.f;
        }
    }
    __syncthreads();

    // suppression bitmask (skip fully-below-diagonal words)
    for (int task = tid; task < TOPK * SUPW; task += blockDim.x) {
        int i = task / SUPW;
        int wj = task - i * SUPW;
        int j0 = wj * 32;
        if (j0 + 31 <= i) { s_sup[i * SUPW + wj] = 0; continue; }
        float4 bi = s_bx[i];
        float ai = s_ar[i];
        unsigned wb = 0;
        int j1 = min(j0 + 32, TOPK);
        for (int j = j0; j < j1; j++) {
            if (j > i) {
                float4 bj = s_bx[j];
                float xx1 = fmaxf(bi.x, bj.x), yy1 = fmaxf(bi.y, bj.y);
                float xx2 = fminf(bi.z, bj.z), yy2 = fminf(bi.w, bj.w);
                float iw = fmaxf(__fsub_rn(xx2, xx1), 0.0f);
                float ih = fmaxf(__fsub_rn(yy2, yy1), 0.0f);
                float inter = __fmul_rn(iw, ih);
                float uni = __fsub_rn(__fadd_rn(ai, s_ar[j]), inter);
                float iou = __fdiv_rn(inter, fmaxf(uni, 1e-9f));
                if (iou > 0.45f) wb |= 1u << (j - j0);
            }
        }
        s_sup[i * SUPW + wj] = wb;
    }
    __syncthreads();

    // greedy sequential NMS (single warp, exact fori_loop semantics)
    if (tid < 32) {
        unsigned kw = 0;
        if (tid < SUPW) {
            int lo = tid * 32;
            int nb = M - lo;
            if (nb > 32) nb = 32;
            if (nb < 0) nb = 0;
            kw = (nb >= 32) ? 0xFFFFFFFFu : ((nb <= 0) ? 0u : ((1u << nb) - 1u));
        }
        for (int i = 0; i < TOPK; i++) {
            unsigned srcw = __shfl_sync(0xFFFFFFFFu, kw, i >> 5);
            if ((srcw >> (i & 31)) & 1u) {
                if (tid < SUPW) kw &= ~s_sup[i * SUPW + tid];
            }
        }
        if (tid < SUPW) keepw[tid] = kw;
    }
    __syncthreads();
    if (tid == 0) {
        int run = 0;
        for (int w = 0; w < SUPW; w++) {
            unsigned x = keepw[w];
            if (run >= KEEPK) {
                x = 0;
            } else {
                int need = KEEPK - run;
                while (__popc(x) > need) x &= ~(1u << (31 - __clz(x)));
            }
            pref_keep[w] = run;
            run += __popc(x);
            keepw[w] = x;
        }
        g_kc[bc] = run;
    }
    __syncthreads();
    for (int t = tid; t < TOPK; t += blockDim.x) {
        unsigned w = keepw[t >> 5];
        if ((w >> (t & 31)) & 1u) {
            int slot = pref_keep[t >> 5] + __popc(w & ((1u << (t & 31)) - 1u));
            int flat = cc * TOPK + t;
            g_ck[bc * KEEPK + slot] =
                ((unsigned long long)__float_as_uint(s_sc[t]) << 32) |
                (unsigned)(0xFFFFFFFFu - (unsigned)flat);
            g_fb[b * (CM1 * TOPK) + flat] = s_bx[t];
        }
    }
}

// ---------------- K4: per-batch global top-200 + emit ----------------------
#define K4_NARR (CM1 * KEEPK)
#define K4_SMEM (K4_NARR * 8 + 256 * 8)
__global__ void __launch_bounds__(1024) k_final(float* __restrict__ out) {
    extern __shared__ unsigned char smraw[];
    unsigned long long* arr = (unsigned long long*)smraw;
    unsigned long long* s_srt = (unsigned long long*)smraw;   // alias
    unsigned long long* arr2 = (unsigned long long*)(smraw + K4_NARR * 8);
    __shared__ int hist[64];
    __shared__ unsigned long long sh_pref;
    __shared__ int sh_b, sh_k, sh_c, sh_cpos;
    __shared__ int off[CM1 + 1];
    int b = blockIdx.x, tid = threadIdx.x;

    if (tid == 0) {
        int run = 0;
        for (int c = 0; c < CM1; c++) { off[c] = run; run += g_kc[b * CM1 + c]; }
        off[CM1] = run;
        sh_cpos = 0;
    }
    __syncthreads();
    int total = off[CM1];
    // single parallel gather with binary search over class offsets
    for (int t = tid; t < total; t += blockDim.x) {
        int lo = 0, hi = CM1 - 1;
        while (lo < hi) {
            int mid = (lo + hi + 1) >> 1;
            if (off[mid] <= t) lo = mid; else hi = mid - 1;
        }
        arr[t] = g_ck[(b * CM1 + lo) * KEEPK + (t - off[lo])];
    }
    __syncthreads();

    int K = min(total, KEEPK);
    unsigned long long kth = 0;
    if (total > KEEPK)
        kth = radix_select_k(arr, total, K, hist, &sh_pref, &sh_b, &sh_k, &sh_c);

    for (int i = tid; i < total; i += blockDim.x) {
        unsigned long long u = arr[i];
        if (u >= kth && u != 0ULL) {
            int pos = atomicAdd(&sh_cpos, 1);
            if (pos < 256) arr2[pos] = u;
        }
    }
    __syncthreads();

    for (int t = tid; t < K; t += blockDim.x) {
        unsigned long long my = arr2[t];
        int rk = 0;
        for (int j = 0; j < K; j++) rk += (arr2[j] > my);
        s_srt[rk] = my;
    }
    __syncthreads();

    for (int t = tid; t < KEEPK; t += blockDim.x) {
        float* row = out + (size_t)(b * KEEPK + t) * 7;
        if (t < K) {
            unsigned long long e = s_srt[t];
            unsigned flat = 0xFFFFFFFFu - (unsigned)(e & 0xFFFFFFFFu);
            float s = __uint_as_float((unsigned)(e >> 32));
            float4 bx = g_fb[b * (CM1 * TOPK) + flat];
            row[0] = (float)b;
            row[1] = (float)(1 + (int)(flat / TOPK));
            row[2] = s;
            row[3] = bx.x;
            row[4] = bx.y;
            row[5] = bx.z;
            row[6] = bx.w;
        } else {
            row[0] = 0.f; row[1] = 0.f; row[2] = 0.f; row[3] = 0.f;
            row[4] = 0.f; row[5] = 0.f; row[6] = 0.f;
        }
    }
}

// ---------------- launch ----------------------------------------------------
extern "C" void kernel_launch(void* const* d_in, const int* in_sizes, int n_in,
                              void* d_out, int out_size) {
    const float* loc = (const float*)d_in[0];
    const float* conf = (const float*)d_in[1];
    const float* prior = (const float*)d_in[2];
    float* out = (float*)d_out;

    cudaFuncSetAttribute(k_select, cudaFuncAttributeMaxDynamicSharedMemorySize, K3_SMEM);
    cudaFuncSetAttribute(k_final, cudaFuncAttributeMaxDynamicSharedMemorySize, K4_SMEM);

    k_thresh<<<NPAIR, 512>>>(conf);
    k_collect<<<BB * 32, 1024>>>(conf);
    k_select<<<NPAIR, 1024, K3_SMEM>>>(loc, prior);
    k_final<<<BB, 1024, K4_SMEM>>>(out);
}

// round 5
// speedup vs baseline: 2.2519x; 2.2519x over previous
#include <cuda_runtime.h>
#include <stdint.h>

#define BB 16
#define PP 131072
#define NC 21
#define CM1 20
#define TOPK 400
#define KEEPK 200
#define GCAP 4608
#define NEGV (-1000000000.0f)
#define SAMP 4096
#define KSEL 64
#define NPAIR (BB * CM1) /* 320 */
#define TILE_P 4096
#define SCAP 192
#define SUPW 13 /* ceil(400/32) */

// ---------------- device scratch ----------------
__device__ float g_tlo[BB][NC];
__device__ int g_cnt[NPAIR];
__device__ unsigned long long g_cand[NPAIR][GCAP];
__device__ int g_kc[NPAIR];
__device__ unsigned long long g_ck[NPAIR * KEEPK];
__device__ float4 g_fb[BB * CM1 * TOPK];

// ---- warp-parallel bucket selection over 64-bucket histogram --------------
__device__ __forceinline__ void warp_bucket_sel(const int* hist, int k,
                                                int* sh_b, int* sh_k, int* sh_c) {
    int lane = threadIdx.x & 31;
    int h0 = hist[2 * lane], h1 = hist[2 * lane + 1];
    int s = h0 + h1;
#pragma unroll
    for (int off = 1; off < 32; off <<= 1) {
        int v = __shfl_down_sync(0xFFFFFFFFu, s, off);
        if (lane + off < 32) s += v;
    }
    int S0 = s, S1 = s - h0;
    int cand = -1, Sc = 0;
    if (S1 >= k)      { cand = 2 * lane + 1; Sc = S1; }
    else if (S0 >= k) { cand = 2 * lane;     Sc = S0; }
    unsigned bal = __ballot_sync(0xFFFFFFFFu, cand >= 0);
    int bsel, cum;
    if (bal) {
        int src = 31 - __clz(bal);
        bsel = __shfl_sync(0xFFFFFFFFu, cand, src);
        int Sb = __shfl_sync(0xFFFFFFFFu, Sc, src);
        cum = Sb - hist[bsel];
    } else {
        int tot = __shfl_sync(0xFFFFFFFFu, S0, 0);
        bsel = 0;
        cum = tot - hist[0];
    }
    if (lane == 0) { *sh_b = bsel; *sh_k = k - cum; *sh_c = hist[bsel]; }
}

// ---- exact k-th largest among n distinct u64 keys (array in L2/global) ----
__device__ unsigned long long radix_select_k(const unsigned long long* __restrict__ arr,
                                             int n, int k,
                                             int* hist, unsigned long long* sh_pref,
                                             int* sh_b, int* sh_k, int* sh_c) {
    int tid = threadIdx.x, bd = blockDim.x;
    unsigned long long prefix = 0, pmask = 0;
    for (int r = 0; r < 11; r++) {
        int shift = 60 - 6 * r;
        if (tid < 64) hist[tid] = 0;
        __syncthreads();
        for (int i = tid; i < n; i += bd) {
            unsigned long long u = arr[i];
            if ((u & pmask) == prefix) atomicAdd(&hist[(int)((u >> shift) & 63)], 1);
        }
        __syncthreads();
        if (tid < 32) warp_bucket_sel(hist, k, sh_b, sh_k, sh_c);
        __syncthreads();
        prefix |= ((unsigned long long)(*sh_b)) << shift;
        k = *sh_k;
        int cnt = *sh_c;
        pmask |= (63ULL << shift);
        if (cnt == 1) {
            __syncthreads();
            for (int i = tid; i < n; i += bd) {
                unsigned long long u = arr[i];
                if ((u & pmask) == prefix) *sh_pref = u;
            }
            __syncthreads();
            return *sh_pref;
        }
    }
    return prefix;
}

// ---------------- K1: per-(b,c) adaptive threshold -------------------------
__global__ void k_thresh(const float* __restrict__ conf) {
    int bc = blockIdx.x;
    int b = bc / CM1, c = bc % CM1 + 1;
    __shared__ unsigned sm[SAMP];
    __shared__ int hist[64];
    __shared__ int sh_b, sh_k, sh_c;
    int tid = threadIdx.x;
    if (tid == 0) g_cnt[bc] = 0;

    const size_t base = (size_t)b * PP * NC + (size_t)c;
    for (int i = tid; i < SAMP; i += blockDim.x) {
        float s = conf[base + (size_t)(i * (PP / SAMP)) * NC];
        sm[i] = __float_as_uint(fmaxf(s, 0.0f));
    }

    unsigned prefix = 0, pmask = 0;
    int k = KSEL;
    for (int r = 0; r < 5; r++) {
        int shift = 26 - 6 * r;
        if (tid < 64) hist[tid] = 0;
        __syncthreads();
        for (int i = tid; i < SAMP; i += blockDim.x) {
            unsigned u = sm[i];
            if ((u & pmask) == prefix) atomicAdd(&hist[(u >> shift) & 63], 1);
        }
        __syncthreads();
        if (tid < 32) warp_bucket_sel(hist, k, &sh_b, &sh_k, &sh_c);
        __syncthreads();
        prefix |= (unsigned)sh_b << shift;
        k = sh_k;
        pmask |= (63u << shift);
    }
    if (tid == 0) g_tlo[b][c] = __uint_as_float(prefix);
}

// ---------------- K2: single coalesced pass over conf ----------------------
__device__ __forceinline__ void k2_push(float s, int e, int pbase,
                                        const float* th, int* scnt,
                                        unsigned long long (*sc)[SCAP], int bbc) {
    int pl = e / NC;
    int c = e - pl * NC;
    if (s >= th[c] && s > 0.01f) {   // th[c] >> 0.01 in practice: rare path first
        int cc = c - 1;
        unsigned long long ent =
            ((unsigned long long)__float_as_uint(s) << 32) |
            (unsigned)(0xFFFFFFFFu - (unsigned)(pbase + pl));
        int pos = atomicAdd(&scnt[cc], 1);
        if (pos < SCAP) {
            sc[cc][pos] = ent;
        } else {
            int gp = atomicAdd(&g_cnt[bbc + cc], 1);
            if (gp < GCAP) g_cand[bbc + cc][gp] = ent;
        }
    }
}

__global__ void __launch_bounds__(1024) k_collect(const float* __restrict__ conf) {
    int b = blockIdx.x >> 5;
    int tile = blockIdx.x & 31;
    __shared__ float th[NC];
    __shared__ int scnt[CM1];
    __shared__ unsigned long long sc[CM1][SCAP];
    int tid = threadIdx.x;
    if (tid < NC) th[tid] = (tid == 0) ? 3.0e38f : g_tlo[b][tid];
    if (tid < CM1) scnt[tid] = 0;
    __syncthreads();

    const size_t base = (size_t)b * PP * NC + (size_t)tile * TILE_P * NC;
    const int pbase = tile * TILE_P;
    const int bbc = b * CM1;
    const float4* cp = (const float4*)(conf + base);
    const int NV = TILE_P * NC / 4;
    for (int t = tid; t < NV; t += 1024) {
        float4 v = cp[t];
        int e = 4 * t;
        k2_push(v.x, e, pbase, th, scnt, sc, bbc);
        k2_push(v.y, e + 1, pbase, th, scnt, sc, bbc);
        k2_push(v.z, e + 2, pbase, th, scnt, sc, bbc);
        k2_push(v.w, e + 3, pbase, th, scnt, sc, bbc);
    }
    __syncthreads();
    int w = tid >> 5, lane = tid & 31;
    if (w < CM1) {
        int n = min(scnt[w], SCAP);
        int gb = 0;
        if (lane == 0) gb = atomicAdd(&g_cnt[bbc + w], n);
        gb = __shfl_sync(0xFFFFFFFFu, gb, 0);
        for (int j = lane; j < n; j += 32) {
            int gp = gb + j;
            if (gp < GCAP) g_cand[bbc + w][gp] = sc[w][j];
        }
    }
}

// ---------------- K3: per-(b,c) top-400 select + decode + NMS --------------
// dyn smem: arr2[512] u64 | s_srt[512] u64 | s_sc[400] | s_bx[400] f4 |
//           s_ar[400] | s_sup[400*13] u32   (~38.6 KB, 4 CTA/SM w/ 512 thr)
#define OFF_SRT   (512 * 8)
#define OFF_SSC   (OFF_SRT + 512 * 8)
#define OFF_SBX   (OFF_SSC + TOPK * 4)
#define OFF_SAR   (OFF_SBX + TOPK * 16)
#define OFF_SUP   (OFF_SAR + TOPK * 4)
#define K3_SMEM   (OFF_SUP + TOPK * SUPW * 4)
__global__ void __launch_bounds__(512) k_select(const float* __restrict__ loc,
                                                const float* __restrict__ prior) {
    extern __shared__ unsigned char smraw[];
    unsigned long long* arr2 = (unsigned long long*)smraw;
    unsigned long long* s_srt = (unsigned long long*)(smraw + OFF_SRT);
    float* s_sc = (float*)(smraw + OFF_SSC);
    float4* s_bx = (float4*)(smraw + OFF_SBX);
    float* s_ar = (float*)(smraw + OFF_SAR);
    unsigned* s_sup = (unsigned*)(smraw + OFF_SUP);
    __shared__ int hist[64];
    __shared__ unsigned long long sh_pref;
    __shared__ int sh_b, sh_k, sh_c, sh_cpos;
    __shared__ unsigned keepw[SUPW];
    __shared__ int pref_keep[SUPW];
    int bc = blockIdx.x;
    int b = bc / CM1, cc = bc % CM1;
    int tid = threadIdx.x, bd = blockDim.x;

    const unsigned long long* gc = g_cand[bc];
    int n = min(g_cnt[bc], GCAP);
    if (tid == 0) sh_cpos = 0;
    __syncthreads();

    int K = min(n, TOPK);
    unsigned long long kth = 0;
    if (n > TOPK) kth = radix_select_k(gc, n, K, hist, &sh_pref, &sh_b, &sh_k, &sh_c);

    for (int i = tid; i < n; i += bd) {
        unsigned long long u = gc[i];
        if (u >= kth && u != 0ULL) {
            int pos = atomicAdd(&sh_cpos, 1);
            if (pos < 512) arr2[pos] = u;
        }
    }
    __syncthreads();

    // rank-sort (distinct keys -> permutation)
    for (int t = tid; t < K; t += bd) {
        unsigned long long my = arr2[t];
        int rk = 0;
        for (int j = 0; j < K; j++) rk += (arr2[j] > my);
        s_srt[rk] = my;
    }
    __syncthreads();

    int M = K;
    const float4* loc4 = (const float4*)loc + (size_t)b * PP;
    const float4* pri4 = (const float4*)prior;
    for (int t = tid; t < TOPK; t += bd) {
        if (t < M) {
            unsigned long long e = s_srt[t];
            unsigned idx = 0xFFFFFFFFu - (unsigned)(e & 0xFFFFFFFFu);
            float4 l = loc4[idx];
            float4 pb = pri4[idx];
            float cx = __fmul_rn(__fadd_rn(pb.x, pb.z), 0.5f);
            float cy = __fmul_rn(__fadd_rn(pb.y, pb.w), 0.5f);
            float swd = __fsub_rn(pb.z, pb.x);
            float shg = __fsub_rn(pb.w, pb.y);
            float x = __fadd_rn(cx, __fmul_rn(__fmul_rn(l.x, 0.1f), swd));
            float y = __fadd_rn(cy, __fmul_rn(__fmul_rn(l.y, 0.1f), shg));
            float w = __fmul_rn(swd, expf(__fmul_rn(l.z, 0.2f)));
            float h = __fmul_rn(shg, expf(__fmul_rn(l.w, 0.2f)));
            float x1 = __fsub_rn(x, __fmul_rn(w, 0.5f));
            float y1 = __fsub_rn(y, __fmul_rn(h, 0.5f));
            float x2 = __fadd_rn(x1, w);
            float y2 = __fadd_rn(y1, h);
            s_sc[t] = __uint_as_float((unsigned)(e >> 32));
            s_bx[t] = make_float4(x1, y1, x2, y2);
            s_ar[t] = __fmul_rn(__fsub_rn(x2, x1), __fsub_rn(y2, y1));
        } else {
            s_sc[t] = NEGV;
            s_bx[t] = make_float4(0.f, 0.f, 0.f, 0.f);
            s_ar[t] = 0.f;
        }
    }
    __syncthreads();

    // suppression bitmask; task = wj*TOPK + i -> warp lanes share wj, j-loads broadcast
    for (int task = tid; task < SUPW * TOPK; task += bd) {
        int wj = task / TOPK;
        int i = task - wj * TOPK;
        int j0 = wj * 32;
        if (j0 + 31 <= i) { s_sup[i * SUPW + wj] = 0; continue; }
        float4 bi = s_bx[i];
        float ai = s_ar[i];
        unsigned wb = 0;
        int j1 = min(j0 + 32, TOPK);
        for (int j = j0; j < j1; j++) {
            if (j > i) {
                float4 bj = s_bx[j];   // warp-uniform -> broadcast
                float xx1 = fmaxf(bi.x, bj.x), yy1 = fmaxf(bi.y, bj.y);
                float xx2 = fminf(bi.z, bj.z), yy2 = fminf(bi.w, bj.w);
                float iw = fmaxf(__fsub_rn(xx2, xx1), 0.0f);
                float ih = fmaxf(__fsub_rn(yy2, yy1), 0.0f);
                float inter = __fmul_rn(iw, ih);
                float uni = __fsub_rn(__fadd_rn(ai, s_ar[j]), inter);
                float maxu = fmaxf(uni, 1e-9f);
                // exact iou>0.45 decision w/o division except in epsilon band
                float diff = __fsub_rn(inter, __fmul_rn(0.45f, maxu));
                bool sup;
                if (fabsf(diff) > __fmul_rn(1e-5f, maxu))
                    sup = diff > 0.0f;
                else
                    sup = __fdiv_rn(inter, maxu) > 0.45f;
                if (sup) wb |= 1u << (j - j0);
            }
        }
        s_sup[i * SUPW + wj] = wb;
    }
    __syncthreads();

    // greedy sequential NMS (single warp, exact fori_loop semantics)
    if (tid < 32) {
        unsigned kw = 0;
        if (tid < SUPW) {
            int lo = tid * 32;
            int nb = M - lo;
            if (nb > 32) nb = 32;
            if (nb < 0) nb = 0;
            kw = (nb >= 32) ? 0xFFFFFFFFu : ((nb <= 0) ? 0u : ((1u << nb) - 1u));
        }
        for (int i = 0; i < TOPK; i++) {
            unsigned srcw = __shfl_sync(0xFFFFFFFFu, kw, i >> 5);
            if ((srcw >> (i & 31)) & 1u) {
                if (tid < SUPW) kw &= ~s_sup[i * SUPW + tid];
            }
        }
        if (tid < SUPW) keepw[tid] = kw;
    }
    __syncthreads();
    if (tid == 0) {
        int run = 0;
        for (int w = 0; w < SUPW; w++) {
            unsigned x = keepw[w];
            if (run >= KEEPK) {
                x = 0;
            } else {
                int need = KEEPK - run;
                while (__popc(x) > need) x &= ~(1u << (31 - __clz(x)));
            }
            pref_keep[w] = run;
            run += __popc(x);
            keepw[w] = x;
        }
        g_kc[bc] = run;
    }
    __syncthreads();
    for (int t = tid; t < TOPK; t += bd) {
        unsigned w = keepw[t >> 5];
        if ((w >> (t & 31)) & 1u) {
            int slot = pref_keep[t >> 5] + __popc(w & ((1u << (t & 31)) - 1u));
            int flat = cc * TOPK + t;
            g_ck[bc * KEEPK + slot] =
                ((unsigned long long)__float_as_uint(s_sc[t]) << 32) |
                (unsigned)(0xFFFFFFFFu - (unsigned)flat);
            g_fb[b * (CM1 * TOPK) + flat] = s_bx[t];
        }
    }
}

// ---------------- K4: per-batch global top-200 + emit ----------------------
#define K4_NARR (CM1 * KEEPK)
#define K4_SMEM (K4_NARR * 8 + 256 * 8)
__global__ void __launch_bounds__(1024) k_final(float* __restrict__ out) {
    extern __shared__ unsigned char smraw[];
    unsigned long long* arr = (unsigned long long*)smraw;
    unsigned long long* s_srt = (unsigned long long*)smraw;   // alias (arr dead at sort)
    unsigned long long* arr2 = (unsigned long long*)(smraw + K4_NARR * 8);
    __shared__ int hist[64];
    __shared__ unsigned long long sh_pref;
    __shared__ int sh_b, sh_k, sh_c, sh_cpos;
    __shared__ int off[CM1 + 1];
    int b = blockIdx.x, tid = threadIdx.x;

    if (tid < 32) {
        int v = (tid < CM1) ? g_kc[b * CM1 + tid] : 0;
        int x = v;
#pragma unroll
        for (int o = 1; o < 32; o <<= 1) {
            int y = __shfl_up_sync(0xFFFFFFFFu, x, o);
            if ((tid & 31) >= o) x += y;
        }
        if (tid < CM1) off[tid] = x - v;
        if (tid == CM1 - 1) off[CM1] = x;
        if (tid == 0) sh_cpos = 0;
    }
    __syncthreads();
    int total = off[CM1];
    for (int t = tid; t < total; t += blockDim.x) {
        int lo = 0, hi = CM1 - 1;
        while (lo < hi) {
            int mid = (lo + hi + 1) >> 1;
            if (off[mid] <= t) lo = mid; else hi = mid - 1;
        }
        arr[t] = g_ck[(b * CM1 + lo) * KEEPK + (t - off[lo])];
    }
    __syncthreads();

    int K = min(total, KEEPK);
    unsigned long long kth = 0;
    if (total > KEEPK)
        kth = radix_select_k(arr, total, K, hist, &sh_pref, &sh_b, &sh_k, &sh_c);

    for (int i = tid; i < total; i += blockDim.x) {
        unsigned long long u = arr[i];
        if (u >= kth && u != 0ULL) {
            int pos = atomicAdd(&sh_cpos, 1);
            if (pos < 256) arr2[pos] = u;
        }
    }
    __syncthreads();

    for (int t = tid; t < K; t += blockDim.x) {
        unsigned long long my = arr2[t];
        int rk = 0;
        for (int j = 0; j < K; j++) rk += (arr2[j] > my);
        s_srt[rk] = my;
    }
    __syncthreads();

    for (int t = tid; t < KEEPK; t += blockDim.x) {
        float* row = out + (size_t)(b * KEEPK + t) * 7;
        if (t < K) {
            unsigned long long e = s_srt[t];
            unsigned flat = 0xFFFFFFFFu - (unsigned)(e & 0xFFFFFFFFu);
            float s = __uint_as_float((unsigned)(e >> 32));
            float4 bx = g_fb[b * (CM1 * TOPK) + flat];
            row[0] = (float)b;
            row[1] = (float)(1 + (int)(flat / TOPK));
            row[2] = s;
            row[3] = bx.x;
            row[4] = bx.y;
            row[5] = bx.z;
            row[6] = bx.w;
        } else {
            row[0] = 0.f; row[1] = 0.f; row[2] = 0.f; row[3] = 0.f;
            row[4] = 0.f; row[5] = 0.f; row[6] = 0.f;
        }
    }
}

// ---------------- launch ----------------------------------------------------
extern "C" void kernel_launch(void* const* d_in, const int* in_sizes, int n_in,
                              void* d_out, int out_size) {
    const float* loc = (const float*)d_in[0];
    const float* conf = (const float*)d_in[1];
    const float* prior = (const float*)d_in[2];
    float* out = (float*)d_out;

    cudaFuncSetAttribute(k_select, cudaFuncAttributeMaxDynamicSharedMemorySize, K3_SMEM);
    cudaFuncSetAttribute(k_final, cudaFuncAttributeMaxDynamicSharedMemorySize, K4_SMEM);

    k_thresh<<<NPAIR, 512>>>(conf);
    k_collect<<<BB * 32, 1024>>>(conf);
    k_select<<<NPAIR, 512, K3_SMEM>>>(loc, prior);
    k_final<<<BB, 1024, K4_SMEM>>>(out);
}